// round 2
// baseline (speedup 1.0000x reference)
#include <cuda_runtime.h>
#include <cuda_bf16.h>

// Problem constants (fixed by reference)
#define NN 100000
#define EE 3200000
#define F_IN 512
#define HH 16
#define CC 7
#define CPAD 8

// Scratch (device globals: allocation-free rule)
__device__ float g_deg[NN];
__device__ float g_dinv[NN];
__device__ float g_h1[NN * HH];     // x @ W1
__device__ float g_out1[NN * HH];   // segment-sum accumulator layer 1
__device__ float g_t2[NN * CPAD];   // relu(out1+b1) @ W2 (padded to 8)
__device__ float g_out2[NN * CPAD]; // segment-sum accumulator layer 2

// ---------------------------------------------------------------------------
// deg[i] = 1 (self loop)
__global__ void k_deg_init() {
    int i = blockIdx.x * blockDim.x + threadIdx.x;
    if (i < NN) g_deg[i] = 1.0f;
}

// deg[dst[e]] += 1
__global__ void k_deg_count(const int* __restrict__ dst) {
    int e = blockIdx.x * blockDim.x + threadIdx.x;
    if (e < EE) atomicAdd(&g_deg[dst[e]], 1.0f);
}

// dinv = rsqrt(deg)
__global__ void k_dinv() {
    int i = blockIdx.x * blockDim.x + threadIdx.x;
    if (i < NN) g_dinv[i] = rsqrtf(g_deg[i]);
}

// ---------------------------------------------------------------------------
// h1 = x @ W1 ; out1 = dinv^2 * h1 (self-loop contribution pre-seeded)
// Block: 256 threads = 16 rows x 16 cols. K tiled by 64.
__global__ void k_gemm1(const float* __restrict__ x, const float* __restrict__ W1) {
    __shared__ float xs[16][65];   // padded
    __shared__ float ws[64][16];

    int row0 = blockIdx.x * 16;
    int r = threadIdx.x >> 4;
    int c = threadIdx.x & 15;
    float acc = 0.0f;

    for (int k0 = 0; k0 < F_IN; k0 += 64) {
        // load x tile: 16 rows x 64 cols = 1024 floats, 4 per thread
        #pragma unroll
        for (int j = 0; j < 4; j++) {
            int idx = threadIdx.x + j * 256;
            int rr = idx >> 6, cc = idx & 63;
            xs[rr][cc] = x[(size_t)(row0 + rr) * F_IN + k0 + cc];
        }
        // load W1 tile: 64 x 16 = 1024 floats
        #pragma unroll
        for (int j = 0; j < 4; j++) {
            int idx = threadIdx.x + j * 256;
            int kk = idx >> 4, cc = idx & 15;
            ws[kk][cc] = W1[(size_t)(k0 + kk) * HH + cc];
        }
        __syncthreads();
        #pragma unroll
        for (int kk = 0; kk < 64; kk++)
            acc = fmaf(xs[r][kk], ws[kk][c], acc);
        __syncthreads();
    }

    int row = row0 + r;
    float di = g_dinv[row];
    g_h1[row * HH + c] = acc;
    g_out1[row * HH + c] = di * di * acc;
}

// ---------------------------------------------------------------------------
// Edge scatter layer 1: out1[d] += dinv[s]*dinv[d] * h1[s], 16 floats = 4x float4 atomics
__global__ void k_scatter1(const int* __restrict__ src, const int* __restrict__ dst) {
    int e = blockIdx.x * blockDim.x + threadIdx.x;
    if (e >= EE) return;
    int s = src[e];
    int d = dst[e];
    float w = g_dinv[s] * g_dinv[d];
    const float4* hs = reinterpret_cast<const float4*>(g_h1 + (size_t)s * HH);
    float4* o = reinterpret_cast<float4*>(g_out1 + (size_t)d * HH);
    #pragma unroll
    for (int i = 0; i < 4; i++) {
        float4 v = hs[i];
        float4 m = make_float4(w * v.x, w * v.y, w * v.z, w * v.w);
        atomicAdd(&o[i], m);
    }
}

// ---------------------------------------------------------------------------
// h2 = relu(out1 + b1); t2 = h2 @ W2; out2 = dinv^2 * t2 (self-loop seed). One thread per row.
__global__ void k_transform2(const float* __restrict__ b1, const float* __restrict__ W2) {
    __shared__ float w2s[HH][CPAD];
    __shared__ float b1s[HH];
    if (threadIdx.x < HH * CC) {
        int k = threadIdx.x / CC, c = threadIdx.x % CC;
        w2s[k][c] = W2[threadIdx.x];
    }
    if (threadIdx.x < HH) b1s[threadIdx.x] = b1[threadIdx.x];
    // zero pad column
    if (threadIdx.x < HH) w2s[threadIdx.x][CC] = 0.0f;
    __syncthreads();

    int i = blockIdx.x * blockDim.x + threadIdx.x;
    if (i >= NN) return;

    float h[HH];
    #pragma unroll
    for (int k = 0; k < HH; k++) {
        float v = g_out1[(size_t)i * HH + k] + b1s[k];
        h[k] = v > 0.0f ? v : 0.0f;
    }
    float di = g_dinv[i];
    float dii = di * di;
    #pragma unroll
    for (int c = 0; c < CPAD; c++) {
        float acc = 0.0f;
        #pragma unroll
        for (int k = 0; k < HH; k++)
            acc = fmaf(h[k], w2s[k][c], acc);
        g_t2[(size_t)i * CPAD + c] = acc;
        g_out2[(size_t)i * CPAD + c] = dii * acc;
    }
}

// ---------------------------------------------------------------------------
// Edge scatter layer 2: out2[d] += w * t2[s], 8 floats = 2x float4 atomics
__global__ void k_scatter2(const int* __restrict__ src, const int* __restrict__ dst) {
    int e = blockIdx.x * blockDim.x + threadIdx.x;
    if (e >= EE) return;
    int s = src[e];
    int d = dst[e];
    float w = g_dinv[s] * g_dinv[d];
    const float4* ts = reinterpret_cast<const float4*>(g_t2 + (size_t)s * CPAD);
    float4* o = reinterpret_cast<float4*>(g_out2 + (size_t)d * CPAD);
    #pragma unroll
    for (int i = 0; i < 2; i++) {
        float4 v = ts[i];
        float4 m = make_float4(w * v.x, w * v.y, w * v.z, w * v.w);
        atomicAdd(&o[i], m);
    }
}

// ---------------------------------------------------------------------------
// out[i,c] = log_softmax(out2[i,c] + b2[c])
__global__ void k_finalize(const float* __restrict__ b2, float* __restrict__ out) {
    int i = blockIdx.x * blockDim.x + threadIdx.x;
    if (i >= NN) return;
    float v[CC];
    float m = -1e30f;
    #pragma unroll
    for (int c = 0; c < CC; c++) {
        v[c] = g_out2[(size_t)i * CPAD + c] + b2[c];
        m = fmaxf(m, v[c]);
    }
    float s = 0.0f;
    #pragma unroll
    for (int c = 0; c < CC; c++) s += __expf(v[c] - m);
    float lse = m + __logf(s);
    #pragma unroll
    for (int c = 0; c < CC; c++)
        out[(size_t)i * CC + c] = v[c] - lse;
}

// ---------------------------------------------------------------------------
extern "C" void kernel_launch(void* const* d_in, const int* in_sizes, int n_in,
                              void* d_out, int out_size) {
    const float* x    = (const float*)d_in[0];
    const int* eidx   = (const int*)d_in[1];
    const float* W1   = (const float*)d_in[2];
    const float* b1   = (const float*)d_in[3];
    const float* W2   = (const float*)d_in[4];
    const float* b2   = (const float*)d_in[5];
    float* out        = (float*)d_out;

    const int* src = eidx;        // edge_index[0]
    const int* dst = eidx + EE;   // edge_index[1]

    const int TB = 256;
    k_deg_init<<<(NN + TB - 1) / TB, TB>>>();
    k_deg_count<<<(EE + TB - 1) / TB, TB>>>(dst);
    k_dinv<<<(NN + TB - 1) / TB, TB>>>();
    k_gemm1<<<NN / 16, 256>>>(x, W1);
    k_scatter1<<<(EE + TB - 1) / TB, TB>>>(src, dst);
    k_transform2<<<(NN + TB - 1) / TB, TB>>>(b1, W2);
    k_scatter2<<<(EE + TB - 1) / TB, TB>>>(src, dst);
    k_finalize<<<(NN + TB - 1) / TB, TB>>>(b2, out);
}

// round 3
// speedup vs baseline: 1.4856x; 1.4856x over previous
#include <cuda_runtime.h>
#include <cuda_bf16.h>

// Problem constants (fixed by reference)
#define NN 100000
#define EE 3200000
#define F_IN 512
#define HH 16
#define CC 7
#define CPAD 8

// GEMM1 tiling
#define GR 256   // rows per block
#define KT 32    // k-tile

// Scratch (device globals: allocation-free rule)
__device__ float g_deg[NN];
__device__ float g_dinv[NN];
__device__ float g_h1[NN * HH];     // x @ W1
__device__ float g_out1[NN * HH];   // segment-sum accumulator layer 1
__device__ float g_t2[NN * CPAD];   // relu(out1+b1) @ W2 (padded to 8)
__device__ float g_out2[NN * CPAD]; // segment-sum accumulator layer 2

// ---------------------------------------------------------------------------
__global__ void k_deg_init() {
    int i = blockIdx.x * blockDim.x + threadIdx.x;
    if (i < NN) g_deg[i] = 1.0f;
}

__global__ void k_deg_count(const int* __restrict__ dst) {
    int e = blockIdx.x * blockDim.x + threadIdx.x;
    if (e < EE) atomicAdd(&g_deg[dst[e]], 1.0f);
}

__global__ void k_dinv() {
    int i = blockIdx.x * blockDim.x + threadIdx.x;
    if (i < NN) g_dinv[i] = rsqrtf(g_deg[i]);
}

// ---------------------------------------------------------------------------
// h1 = x @ W1 ; out1 = dinv^2 * h1 (self-loop contribution pre-seeded)
// 256 threads. Block tile: 256 rows x 16 cols. Thread micro-tile: 4 rows x 4 cols.
__global__ void __launch_bounds__(256) k_gemm1(const float* __restrict__ x,
                                               const float* __restrict__ W1) {
    __shared__ float xs[GR][KT + 1];   // stride 33 -> conflict-free row reads
    __shared__ float ws[KT][HH];

    const int t = threadIdx.x;
    const int row0 = blockIdx.x * GR;
    const int rg = t >> 2;       // 0..63  (row group)
    const int c0 = (t & 3) * 4;  // 0,4,8,12

    // global-load mapping: 8 threads per row, each loads one float4
    const int lrow = t >> 3;     // 0..31
    const int lq = (t & 7) * 4;  // col offset 0..28

    float acc[4][4] = {};

    for (int k0 = 0; k0 < F_IN; k0 += KT) {
        // load W1 tile: 32x16 = 512 floats, 2 per thread (coalesced)
        {
            int i0 = t;
            ws[i0 >> 4][i0 & 15] = W1[(size_t)(k0 + (i0 >> 4)) * HH + (i0 & 15)];
            int i1 = t + 256;
            ws[i1 >> 4][i1 & 15] = W1[(size_t)(k0 + (i1 >> 4)) * HH + (i1 & 15)];
        }
        // load x tile: 256 rows x 32 cols, each thread 8 float4 (128B per row-group)
        #pragma unroll
        for (int j = 0; j < 8; j++) {
            int r = lrow + j * 32;
            int grow = row0 + r;
            float4 v = make_float4(0.f, 0.f, 0.f, 0.f);
            if (grow < NN)
                v = *reinterpret_cast<const float4*>(x + (size_t)grow * F_IN + k0 + lq);
            xs[r][lq + 0] = v.x;
            xs[r][lq + 1] = v.y;
            xs[r][lq + 2] = v.z;
            xs[r][lq + 3] = v.w;
        }
        __syncthreads();

        #pragma unroll
        for (int kk = 0; kk < KT; kk++) {
            float4 w = *reinterpret_cast<const float4*>(&ws[kk][c0]);
            #pragma unroll
            for (int i = 0; i < 4; i++) {
                float xv = xs[rg * 4 + i][kk];
                acc[i][0] = fmaf(xv, w.x, acc[i][0]);
                acc[i][1] = fmaf(xv, w.y, acc[i][1]);
                acc[i][2] = fmaf(xv, w.z, acc[i][2]);
                acc[i][3] = fmaf(xv, w.w, acc[i][3]);
            }
        }
        __syncthreads();
    }

    #pragma unroll
    for (int i = 0; i < 4; i++) {
        int row = row0 + rg * 4 + i;
        if (row < NN) {
            float di = g_dinv[row];
            float dii = di * di;
            float4 h = make_float4(acc[i][0], acc[i][1], acc[i][2], acc[i][3]);
            *reinterpret_cast<float4*>(g_h1 + (size_t)row * HH + c0) = h;
            float4 o = make_float4(dii * h.x, dii * h.y, dii * h.z, dii * h.w);
            *reinterpret_cast<float4*>(g_out1 + (size_t)row * HH + c0) = o;
        }
    }
}

// ---------------------------------------------------------------------------
// Edge scatter layer 1: out1[d] += dinv[s]*dinv[d] * h1[s], 16 floats = 4x float4 atomics
__global__ void k_scatter1(const int* __restrict__ src, const int* __restrict__ dst) {
    int e = blockIdx.x * blockDim.x + threadIdx.x;
    if (e >= EE) return;
    int s = src[e];
    int d = dst[e];
    float w = g_dinv[s] * g_dinv[d];
    const float4* hs = reinterpret_cast<const float4*>(g_h1 + (size_t)s * HH);
    float4* o = reinterpret_cast<float4*>(g_out1 + (size_t)d * HH);
    #pragma unroll
    for (int i = 0; i < 4; i++) {
        float4 v = hs[i];
        float4 m = make_float4(w * v.x, w * v.y, w * v.z, w * v.w);
        atomicAdd(&o[i], m);
    }
}

// ---------------------------------------------------------------------------
// h2 = relu(out1 + b1); t2 = h2 @ W2; out2 = dinv^2 * t2 (self-loop seed).
__global__ void k_transform2(const float* __restrict__ b1, const float* __restrict__ W2) {
    __shared__ float w2s[HH][CPAD];
    __shared__ float b1s[HH];
    if (threadIdx.x < HH * CC) {
        int k = threadIdx.x / CC, c = threadIdx.x % CC;
        w2s[k][c] = W2[threadIdx.x];
    }
    if (threadIdx.x < HH) b1s[threadIdx.x] = b1[threadIdx.x];
    if (threadIdx.x < HH) w2s[threadIdx.x][CC] = 0.0f;
    __syncthreads();

    int i = blockIdx.x * blockDim.x + threadIdx.x;
    if (i >= NN) return;

    float h[HH];
    #pragma unroll
    for (int k = 0; k < HH; k++) {
        float v = g_out1[(size_t)i * HH + k] + b1s[k];
        h[k] = v > 0.0f ? v : 0.0f;
    }
    float di = g_dinv[i];
    float dii = di * di;
    #pragma unroll
    for (int c = 0; c < CPAD; c++) {
        float acc = 0.0f;
        #pragma unroll
        for (int k = 0; k < HH; k++)
            acc = fmaf(h[k], w2s[k][c], acc);
        g_t2[(size_t)i * CPAD + c] = acc;
        g_out2[(size_t)i * CPAD + c] = dii * acc;
    }
}

// ---------------------------------------------------------------------------
// Edge scatter layer 2: out2[d] += w * t2[s], 8 floats = 2x float4 atomics
__global__ void k_scatter2(const int* __restrict__ src, const int* __restrict__ dst) {
    int e = blockIdx.x * blockDim.x + threadIdx.x;
    if (e >= EE) return;
    int s = src[e];
    int d = dst[e];
    float w = g_dinv[s] * g_dinv[d];
    const float4* ts = reinterpret_cast<const float4*>(g_t2 + (size_t)s * CPAD);
    float4* o = reinterpret_cast<float4*>(g_out2 + (size_t)d * CPAD);
    #pragma unroll
    for (int i = 0; i < 2; i++) {
        float4 v = ts[i];
        float4 m = make_float4(w * v.x, w * v.y, w * v.z, w * v.w);
        atomicAdd(&o[i], m);
    }
}

// ---------------------------------------------------------------------------
// out[i,c] = log_softmax(out2[i,c] + b2[c])
__global__ void k_finalize(const float* __restrict__ b2, float* __restrict__ out) {
    int i = blockIdx.x * blockDim.x + threadIdx.x;
    if (i >= NN) return;
    float v[CC];
    float m = -1e30f;
    #pragma unroll
    for (int c = 0; c < CC; c++) {
        v[c] = g_out2[(size_t)i * CPAD + c] + b2[c];
        m = fmaxf(m, v[c]);
    }
    float s = 0.0f;
    #pragma unroll
    for (int c = 0; c < CC; c++) s += __expf(v[c] - m);
    float lse = m + __logf(s);
    #pragma unroll
    for (int c = 0; c < CC; c++)
        out[(size_t)i * CC + c] = v[c] - lse;
}

// ---------------------------------------------------------------------------
extern "C" void kernel_launch(void* const* d_in, const int* in_sizes, int n_in,
                              void* d_out, int out_size) {
    const float* x    = (const float*)d_in[0];
    const int* eidx   = (const int*)d_in[1];
    const float* W1   = (const float*)d_in[2];
    const float* b1   = (const float*)d_in[3];
    const float* W2   = (const float*)d_in[4];
    const float* b2   = (const float*)d_in[5];
    float* out        = (float*)d_out;

    const int* src = eidx;        // edge_index[0]
    const int* dst = eidx + EE;   // edge_index[1]

    const int TB = 256;
    k_deg_init<<<(NN + TB - 1) / TB, TB>>>();
    k_deg_count<<<(EE + TB - 1) / TB, TB>>>(dst);
    k_dinv<<<(NN + TB - 1) / TB, TB>>>();
    k_gemm1<<<(NN + GR - 1) / GR, 256>>>(x, W1);
    k_scatter1<<<(EE + TB - 1) / TB, TB>>>(src, dst);
    k_transform2<<<(NN + TB - 1) / TB, TB>>>(b1, W2);
    k_scatter2<<<(EE + TB - 1) / TB, TB>>>(src, dst);
    k_finalize<<<(NN + TB - 1) / TB, TB>>>(b2, out);
}

// round 4
// speedup vs baseline: 1.7946x; 1.2080x over previous
#include <cuda_runtime.h>
#include <cuda_bf16.h>

// Problem constants (fixed by reference)
#define NN 100000
#define EE 3200000
#define F_IN 512
#define HH 16
#define CC 7
#define CPAD 8

// GEMM1 tiling: 128 threads, block tile 256 rows x 16 cols, thread tile 8x4, k-tile 16
#define GR 256
#define KT 16
#define XS_STRIDE 20   // pad: 16B-aligned rows, 8 consecutive rows -> 8 distinct banks

// Scratch (device globals: allocation-free rule)
__device__ float g_deg[NN];
__device__ float g_dinv[NN];
__device__ float g_h1[NN * HH];     // x @ W1
__device__ float g_out1[NN * HH];   // segment-sum accumulator layer 1
__device__ float g_t2[NN * CPAD];   // relu(out1+b1) @ W2 (padded to 8)
__device__ float g_out2[NN * CPAD]; // segment-sum accumulator layer 2

// ---------------------------------------------------------------------------
__global__ void k_deg_init() {
    int i = blockIdx.x * blockDim.x + threadIdx.x;
    if (i < NN) g_deg[i] = 1.0f;
}

__global__ void k_deg_count(const int* __restrict__ dst) {
    int e = blockIdx.x * blockDim.x + threadIdx.x;
    if (e < EE) atomicAdd(&g_deg[dst[e]], 1.0f);
}

__global__ void k_dinv() {
    int i = blockIdx.x * blockDim.x + threadIdx.x;
    if (i < NN) g_dinv[i] = rsqrtf(g_deg[i]);
}

// ---------------------------------------------------------------------------
// h1 = x @ W1 ; out1 = dinv^2 * h1 (self-loop contribution pre-seeded)
// 128 threads. Thread micro-tile: 8 rows (strided by 32) x 4 cols.
__global__ void __launch_bounds__(128) k_gemm1(const float* __restrict__ x,
                                               const float* __restrict__ W1) {
    __shared__ float xs[GR][XS_STRIDE];
    __shared__ float ws[KT][HH];

    const int t = threadIdx.x;
    const int row0 = blockIdx.x * GR;
    const int rg = t >> 2;       // 0..31 (row group; thread rows = rg + 32*i)
    const int c0 = (t & 3) * 4;  // 0,4,8,12

    float acc[8][4] = {};

    for (int k0 = 0; k0 < F_IN; k0 += KT) {
        // load W1 tile: 16x16 = 256 floats, 2 per thread (coalesced)
        {
            int i0 = t;
            ws[i0 >> 4][i0 & 15] = W1[(size_t)(k0 + (i0 >> 4)) * HH + (i0 & 15)];
            int i1 = t + 128;
            ws[i1 >> 4][i1 & 15] = W1[(size_t)(k0 + (i1 >> 4)) * HH + (i1 & 15)];
        }
        // load x tile: 256 rows x 16 cols = 1024 float4, 8 per thread
        #pragma unroll
        for (int j = 0; j < 8; j++) {
            int q = t + j * 128;
            int r = q >> 2;          // 0..255
            int cq = (q & 3) * 4;    // 0,4,8,12
            int grow = row0 + r;
            float4 v = make_float4(0.f, 0.f, 0.f, 0.f);
            if (grow < NN)
                v = *reinterpret_cast<const float4*>(x + (size_t)grow * F_IN + k0 + cq);
            *reinterpret_cast<float4*>(&xs[r][cq]) = v;
        }
        __syncthreads();

        #pragma unroll
        for (int kk = 0; kk < KT; kk++) {
            float4 w = *reinterpret_cast<const float4*>(&ws[kk][c0]);
            #pragma unroll
            for (int i = 0; i < 8; i++) {
                float xv = xs[rg + 32 * i][kk];
                acc[i][0] = fmaf(xv, w.x, acc[i][0]);
                acc[i][1] = fmaf(xv, w.y, acc[i][1]);
                acc[i][2] = fmaf(xv, w.z, acc[i][2]);
                acc[i][3] = fmaf(xv, w.w, acc[i][3]);
            }
        }
        __syncthreads();
    }

    #pragma unroll
    for (int i = 0; i < 8; i++) {
        int row = row0 + rg + 32 * i;
        if (row < NN) {
            float di = g_dinv[row];
            float dii = di * di;
            float4 h = make_float4(acc[i][0], acc[i][1], acc[i][2], acc[i][3]);
            *reinterpret_cast<float4*>(g_h1 + (size_t)row * HH + c0) = h;
            float4 o = make_float4(dii * h.x, dii * h.y, dii * h.z, dii * h.w);
            *reinterpret_cast<float4*>(g_out1 + (size_t)row * HH + c0) = o;
        }
    }
}

// ---------------------------------------------------------------------------
// Edge scatter layer 1: 4 threads per edge, each handles one float4 slice.
__global__ void __launch_bounds__(256) k_scatter1(const int* __restrict__ src,
                                                  const int* __restrict__ dst) {
    int tid = blockIdx.x * blockDim.x + threadIdx.x;
    int e = tid >> 2;
    int p = tid & 3;
    if (e >= EE) return;
    int s = src[e];
    int d = dst[e];
    float w = g_dinv[s] * g_dinv[d];
    float4 v = *reinterpret_cast<const float4*>(g_h1 + (size_t)s * HH + p * 4);
    float4 m = make_float4(w * v.x, w * v.y, w * v.z, w * v.w);
    atomicAdd(reinterpret_cast<float4*>(g_out1 + (size_t)d * HH + p * 4), m);
}

// ---------------------------------------------------------------------------
// h2 = relu(out1 + b1); t2 = h2 @ W2; out2 = dinv^2 * t2 (self-loop seed).
__global__ void k_transform2(const float* __restrict__ b1, const float* __restrict__ W2) {
    __shared__ float w2s[HH][CPAD];
    __shared__ float b1s[HH];
    if (threadIdx.x < HH * CC) {
        int k = threadIdx.x / CC, c = threadIdx.x % CC;
        w2s[k][c] = W2[threadIdx.x];
    }
    if (threadIdx.x < HH) b1s[threadIdx.x] = b1[threadIdx.x];
    if (threadIdx.x < HH) w2s[threadIdx.x][CC] = 0.0f;
    __syncthreads();

    int i = blockIdx.x * blockDim.x + threadIdx.x;
    if (i >= NN) return;

    float h[HH];
    #pragma unroll
    for (int k = 0; k < HH; k++) {
        float v = g_out1[(size_t)i * HH + k] + b1s[k];
        h[k] = v > 0.0f ? v : 0.0f;
    }
    float di = g_dinv[i];
    float dii = di * di;
    #pragma unroll
    for (int c = 0; c < CPAD; c++) {
        float acc = 0.0f;
        #pragma unroll
        for (int k = 0; k < HH; k++)
            acc = fmaf(h[k], w2s[k][c], acc);
        g_t2[(size_t)i * CPAD + c] = acc;
        g_out2[(size_t)i * CPAD + c] = dii * acc;
    }
}

// ---------------------------------------------------------------------------
// Edge scatter layer 2: 2 threads per edge, one float4 slice each.
__global__ void __launch_bounds__(256) k_scatter2(const int* __restrict__ src,
                                                  const int* __restrict__ dst) {
    int tid = blockIdx.x * blockDim.x + threadIdx.x;
    int e = tid >> 1;
    int p = tid & 1;
    if (e >= EE) return;
    int s = src[e];
    int d = dst[e];
    float w = g_dinv[s] * g_dinv[d];
    float4 v = *reinterpret_cast<const float4*>(g_t2 + (size_t)s * CPAD + p * 4);
    float4 m = make_float4(w * v.x, w * v.y, w * v.z, w * v.w);
    atomicAdd(reinterpret_cast<float4*>(g_out2 + (size_t)d * CPAD + p * 4), m);
}

// ---------------------------------------------------------------------------
// out[i,c] = log_softmax(out2[i,c] + b2[c])
__global__ void k_finalize(const float* __restrict__ b2, float* __restrict__ out) {
    int i = blockIdx.x * blockDim.x + threadIdx.x;
    if (i >= NN) return;
    float v[CC];
    float m = -1e30f;
    #pragma unroll
    for (int c = 0; c < CC; c++) {
        v[c] = g_out2[(size_t)i * CPAD + c] + b2[c];
        m = fmaxf(m, v[c]);
    }
    float s = 0.0f;
    #pragma unroll
    for (int c = 0; c < CC; c++) s += __expf(v[c] - m);
    float lse = m + __logf(s);
    #pragma unroll
    for (int c = 0; c < CC; c++)
        out[(size_t)i * CC + c] = v[c] - lse;
}

// ---------------------------------------------------------------------------
extern "C" void kernel_launch(void* const* d_in, const int* in_sizes, int n_in,
                              void* d_out, int out_size) {
    const float* x    = (const float*)d_in[0];
    const int* eidx   = (const int*)d_in[1];
    const float* W1   = (const float*)d_in[2];
    const float* b1   = (const float*)d_in[3];
    const float* W2   = (const float*)d_in[4];
    const float* b2   = (const float*)d_in[5];
    float* out        = (float*)d_out;

    const int* src = eidx;        // edge_index[0]
    const int* dst = eidx + EE;   // edge_index[1]

    const int TB = 256;
    k_deg_init<<<(NN + TB - 1) / TB, TB>>>();
    k_deg_count<<<(EE + TB - 1) / TB, TB>>>(dst);
    k_dinv<<<(NN + TB - 1) / TB, TB>>>();
    k_gemm1<<<(NN + GR - 1) / GR, 128>>>(x, W1);
    k_scatter1<<<(EE * 4) / TB, TB>>>(src, dst);
    k_transform2<<<(NN + TB - 1) / TB, TB>>>(b1, W2);
    k_scatter2<<<(EE * 2) / TB, TB>>>(src, dst);
    k_finalize<<<(NN + TB - 1) / TB, TB>>>(b2, out);
}

// round 6
// speedup vs baseline: 1.8993x; 1.0583x over previous
#include <cuda_runtime.h>
#include <cuda_bf16.h>
#include <cstdint>

// Problem constants (fixed by reference)
#define NN 100000
#define EE 3200000
#define F_IN 512
#define HH 16
#define CC 7
#define CPAD 8

// GEMM1 tiling: 256 threads, block tile 256 rows x 16 cols, thread tile 4x4, k-tile 16
#define GR 256
#define KT 16
#define NTILES (F_IN / KT)
#define XSS 20   // xs row stride: 16B-aligned, 8 consecutive rows hit 8 distinct banks

// Scratch (device globals: allocation-free rule)
__device__ float g_deg[NN];
__device__ float g_dinv[NN];
__device__ float g_h1[NN * HH];     // x @ W1
__device__ float g_out1[NN * HH];   // segment-sum accumulator layer 1
__device__ float g_t2[NN * CPAD];   // relu(out1+b1) @ W2 (padded to 8)
__device__ float g_out2[NN * CPAD]; // segment-sum accumulator layer 2

#define CP_ASYNC16(smem_u32, gptr, valid)                                   \
    asm volatile("cp.async.cg.shared.global [%0], [%1], 16, %2;\n"          \
                 :: "r"(smem_u32), "l"(gptr), "r"((valid) ? 16 : 0))
#define CP_COMMIT() asm volatile("cp.async.commit_group;\n")
#define CP_WAIT(n)  asm volatile("cp.async.wait_group %0;\n" :: "n"(n))

// ---------------------------------------------------------------------------
__global__ void k_deg_init() {
    int i = blockIdx.x * blockDim.x + threadIdx.x;
    if (i < NN) g_deg[i] = 1.0f;
}

__global__ void k_deg_count(const int* __restrict__ dst) {
    int e = blockIdx.x * blockDim.x + threadIdx.x;
    if (e < EE) atomicAdd(&g_deg[dst[e]], 1.0f);
}

__global__ void k_dinv() {
    int i = blockIdx.x * blockDim.x + threadIdx.x;
    if (i < NN) g_dinv[i] = rsqrtf(g_deg[i]);
}

// ---------------------------------------------------------------------------
// h1 = x @ W1 ; out1 = dinv^2 * h1 (self-loop contribution pre-seeded)
// 2-stage cp.async pipeline; thread tile 4 rows (stride 64) x 4 cols.
__global__ void __launch_bounds__(256) k_gemm1(const float* __restrict__ x,
                                               const float* __restrict__ W1) {
    __shared__ float xs[2][GR][XSS];
    __shared__ float ws[2][KT][HH];

    const int t = threadIdx.x;
    const int row0 = blockIdx.x * GR;
    const int rg = t >> 2;       // 0..63 (thread rows = rg + 64*i)
    const int c0 = (t & 3) * 4;  // 0,4,8,12

    auto issue_tile = [&](int tile, int buf) {
        int k0 = tile * KT;
        #pragma unroll
        for (int j = 0; j < 4; j++) {
            int q = t + j * 256;
            int r = q >> 2;
            int cq = (q & 3) * 4;
            int grow = row0 + r;
            unsigned int sa = (unsigned int)__cvta_generic_to_shared(&xs[buf][r][cq]);
            CP_ASYNC16(sa, x + (size_t)grow * F_IN + k0 + cq, grow < NN);
        }
        if (t < 64) {
            int r = t >> 2;
            int cq = (t & 3) * 4;
            unsigned int sa = (unsigned int)__cvta_generic_to_shared(&ws[buf][r][cq]);
            CP_ASYNC16(sa, W1 + (size_t)(k0 + r) * HH + cq, 1);
        }
    };

    float acc[4][4] = {};

    issue_tile(0, 0);
    CP_COMMIT();

    #pragma unroll 4
    for (int it = 0; it < NTILES; it++) {
        int buf = it & 1;
        if (it + 1 < NTILES) {
            issue_tile(it + 1, buf ^ 1);
            CP_COMMIT();
            CP_WAIT(1);
        } else {
            CP_WAIT(0);
        }
        __syncthreads();

        #pragma unroll
        for (int kk = 0; kk < KT; kk++) {
            float4 w = *reinterpret_cast<const float4*>(&ws[buf][kk][c0]);
            #pragma unroll
            for (int i = 0; i < 4; i++) {
                float xv = xs[buf][rg + 64 * i][kk];
                acc[i][0] = fmaf(xv, w.x, acc[i][0]);
                acc[i][1] = fmaf(xv, w.y, acc[i][1]);
                acc[i][2] = fmaf(xv, w.z, acc[i][2]);
                acc[i][3] = fmaf(xv, w.w, acc[i][3]);
            }
        }
        __syncthreads();
    }

    #pragma unroll
    for (int i = 0; i < 4; i++) {
        int row = row0 + rg + 64 * i;
        if (row < NN) {
            float di = g_dinv[row];
            float dii = di * di;
            float4 h = make_float4(acc[i][0], acc[i][1], acc[i][2], acc[i][3]);
            *reinterpret_cast<float4*>(g_h1 + (size_t)row * HH + c0) = h;
            float4 o = make_float4(dii * h.x, dii * h.y, dii * h.z, dii * h.w);
            *reinterpret_cast<float4*>(g_out1 + (size_t)row * HH + c0) = o;
        }
    }
}

// ---------------------------------------------------------------------------
// Edge scatter layer 1: 4 threads per edge, each handles one float4 slice.
__global__ void __launch_bounds__(256) k_scatter1(const int* __restrict__ src,
                                                  const int* __restrict__ dst) {
    int tid = blockIdx.x * blockDim.x + threadIdx.x;
    int e = tid >> 2;
    int p = tid & 3;
    if (e >= EE) return;
    int s = src[e];
    int d = dst[e];
    float w = g_dinv[s] * g_dinv[d];
    float4 v = *reinterpret_cast<const float4*>(g_h1 + (size_t)s * HH + p * 4);
    float4 m = make_float4(w * v.x, w * v.y, w * v.z, w * v.w);
    atomicAdd(reinterpret_cast<float4*>(g_out1 + (size_t)d * HH + p * 4), m);
}

// ---------------------------------------------------------------------------
// h2 = relu(out1 + b1); t2 = h2 @ W2; out2 = dinv^2 * t2 (self-loop seed).
__global__ void k_transform2(const float* __restrict__ b1, const float* __restrict__ W2) {
    __shared__ float w2s[HH][CPAD];
    __shared__ float b1s[HH];
    if (threadIdx.x < HH * CC) {
        int k = threadIdx.x / CC, c = threadIdx.x % CC;
        w2s[k][c] = W2[threadIdx.x];
    }
    if (threadIdx.x < HH) b1s[threadIdx.x] = b1[threadIdx.x];
    if (threadIdx.x < HH) w2s[threadIdx.x][CC] = 0.0f;
    __syncthreads();

    int i = blockIdx.x * blockDim.x + threadIdx.x;
    if (i >= NN) return;

    float h[HH];
    #pragma unroll
    for (int k = 0; k < HH; k++) {
        float v = g_out1[(size_t)i * HH + k] + b1s[k];
        h[k] = v > 0.0f ? v : 0.0f;
    }
    float di = g_dinv[i];
    float dii = di * di;
    #pragma unroll
    for (int c = 0; c < CPAD; c++) {
        float acc = 0.0f;
        #pragma unroll
        for (int k = 0; k < HH; k++)
            acc = fmaf(h[k], w2s[k][c], acc);
        g_t2[(size_t)i * CPAD + c] = acc;
        g_out2[(size_t)i * CPAD + c] = dii * acc;
    }
}

// ---------------------------------------------------------------------------
// Edge scatter layer 2: 2 threads per edge, one float4 slice each.
__global__ void __launch_bounds__(256) k_scatter2(const int* __restrict__ src,
                                                  const int* __restrict__ dst) {
    int tid = blockIdx.x * blockDim.x + threadIdx.x;
    int e = tid >> 1;
    int p = tid & 1;
    if (e >= EE) return;
    int s = src[e];
    int d = dst[e];
    float w = g_dinv[s] * g_dinv[d];
    float4 v = *reinterpret_cast<const float4*>(g_t2 + (size_t)s * CPAD + p * 4);
    float4 m = make_float4(w * v.x, w * v.y, w * v.z, w * v.w);
    atomicAdd(reinterpret_cast<float4*>(g_out2 + (size_t)d * CPAD + p * 4), m);
}

// ---------------------------------------------------------------------------
// out[i,c] = log_softmax(out2[i,c] + b2[c])
__global__ void k_finalize(const float* __restrict__ b2, float* __restrict__ out) {
    int i = blockIdx.x * blockDim.x + threadIdx.x;
    if (i >= NN) return;
    float v[CC];
    float m = -1e30f;
    #pragma unroll
    for (int c = 0; c < CC; c++) {
        v[c] = g_out2[(size_t)i * CPAD + c] + b2[c];
        m = fmaxf(m, v[c]);
    }
    float s = 0.0f;
    #pragma unroll
    for (int c = 0; c < CC; c++) s += __expf(v[c] - m);
    float lse = m + __logf(s);
    #pragma unroll
    for (int c = 0; c < CC; c++)
        out[(size_t)i * CC + c] = v[c] - lse;
}

// ---------------------------------------------------------------------------
extern "C" void kernel_launch(void* const* d_in, const int* in_sizes, int n_in,
                              void* d_out, int out_size) {
    const float* x    = (const float*)d_in[0];
    const int* eidx   = (const int*)d_in[1];
    const float* W1   = (const float*)d_in[2];
    const float* b1   = (const float*)d_in[3];
    const float* W2   = (const float*)d_in[4];
    const float* b2   = (const float*)d_in[5];
    float* out        = (float*)d_out;

    const int* src = eidx;        // edge_index[0]
    const int* dst = eidx + EE;   // edge_index[1]

    const int TB = 256;
    k_deg_init<<<(NN + TB - 1) / TB, TB>>>();
    k_deg_count<<<(EE + TB - 1) / TB, TB>>>(dst);
    k_dinv<<<(NN + TB - 1) / TB, TB>>>();
    k_gemm1<<<(NN + GR - 1) / GR, 256>>>(x, W1);
    k_scatter1<<<(EE * 4) / TB, TB>>>(src, dst);
    k_transform2<<<(NN + TB - 1) / TB, TB>>>(b1, W2);
    k_scatter2<<<(EE * 2) / TB, TB>>>(src, dst);
    k_finalize<<<(NN + TB - 1) / TB, TB>>>(b2, out);
}

// round 7
// speedup vs baseline: 2.0294x; 1.0685x over previous
#include <cuda_runtime.h>
#include <cuda_bf16.h>
#include <cstdint>

// Problem constants (fixed by reference)
#define NN 100000
#define EE 3200000
#define F_IN 512
#define HH 16
#define CC 7
#define CPAD 8

// GEMM1 tiling
#define GR 256
#define KT 16
#define NTILES (F_IN / KT)
#define XSS 20

// Scan config
#define SB 512
#define NSB ((NN + SB - 1) / SB)   // 196

// Scratch (device globals: allocation-free rule)
__device__ int   g_cnt[NN];        // in-degree (excl self loop)
__device__ int   g_cursor[NN];     // permute cursors
__device__ int   g_rowptr[NN + 1]; // CSR row pointers (by dst)
__device__ int   g_bsum[NSB];
__device__ int   g_boff[NSB];
__device__ float g_dinv[NN];
__device__ int   g_csrc[EE];       // CSR src indices
__device__ float g_h1[NN * HH];    // x @ W1
__device__ float g_out1[NN * HH];  // layer-1 aggregated output
__device__ float g_t2[NN * CPAD];  // relu(out1+b1) @ W2

#define CP_ASYNC16(smem_u32, gptr, valid)                                   \
    asm volatile("cp.async.cg.shared.global [%0], [%1], 16, %2;\n"          \
                 :: "r"(smem_u32), "l"(gptr), "r"((valid) ? 16 : 0))
#define CP_COMMIT() asm volatile("cp.async.commit_group;\n")
#define CP_WAIT(n)  asm volatile("cp.async.wait_group %0;\n" :: "n"(n))

// ---------------------------------------------------------------------------
__global__ void k_prep0() {
    int i = blockIdx.x * blockDim.x + threadIdx.x;
    if (i < NN) { g_cnt[i] = 0; g_cursor[i] = 0; }
}

__global__ void k_hist(const int* __restrict__ dst) {
    int e = blockIdx.x * blockDim.x + threadIdx.x;
    if (e < EE) atomicAdd(&g_cnt[dst[e]], 1);
}

// Block-local exclusive scan (Hillis-Steele) + block sums
__global__ void __launch_bounds__(SB) k_scan1() {
    __shared__ int sh[SB];
    int t = threadIdx.x;
    int i = blockIdx.x * SB + t;
    int v = (i < NN) ? g_cnt[i] : 0;
    sh[t] = v;
    __syncthreads();
    #pragma unroll
    for (int off = 1; off < SB; off <<= 1) {
        int add = (t >= off) ? sh[t - off] : 0;
        __syncthreads();
        sh[t] += add;
        __syncthreads();
    }
    if (i < NN) g_rowptr[i] = sh[t] - v;   // exclusive
    if (t == SB - 1) g_bsum[blockIdx.x] = sh[SB - 1];
}

// Scan the block sums (NSB=196 <= 256) in one block
__global__ void __launch_bounds__(256) k_scan2() {
    __shared__ int sh[256];
    int t = threadIdx.x;
    int v = (t < NSB) ? g_bsum[t] : 0;
    sh[t] = v;
    __syncthreads();
    #pragma unroll
    for (int off = 1; off < 256; off <<= 1) {
        int add = (t >= off) ? sh[t - off] : 0;
        __syncthreads();
        sh[t] += add;
        __syncthreads();
    }
    if (t < NSB) g_boff[t] = sh[t] - v;    // exclusive
}

// Add block offsets; compute dinv = rsqrt(cnt + 1 self loop)
__global__ void k_scan3() {
    int i = blockIdx.x * blockDim.x + threadIdx.x;
    if (i < NN) {
        g_rowptr[i] += g_boff[i / SB];
        g_dinv[i] = rsqrtf((float)g_cnt[i] + 1.0f);
    }
    if (i == 0) g_rowptr[NN] = EE;
}

// Permute edges into CSR-by-dst
__global__ void k_permute(const int* __restrict__ src, const int* __restrict__ dst) {
    int e = blockIdx.x * blockDim.x + threadIdx.x;
    if (e >= EE) return;
    int d = dst[e];
    int pos = g_rowptr[d] + atomicAdd(&g_cursor[d], 1);
    g_csrc[pos] = src[e];
}

// ---------------------------------------------------------------------------
// h1 = x @ W1 (no normalization here). 2-stage cp.async pipeline, 4x4 thread tile.
__global__ void __launch_bounds__(256, 4) k_gemm1(const float* __restrict__ x,
                                                  const float* __restrict__ W1) {
    __shared__ float xs[2][GR][XSS];
    __shared__ float ws[2][KT][HH];

    const int t = threadIdx.x;
    const int row0 = blockIdx.x * GR;
    const int rg = t >> 2;
    const int c0 = (t & 3) * 4;

    auto issue_tile = [&](int tile, int buf) {
        int k0 = tile * KT;
        #pragma unroll
        for (int j = 0; j < 4; j++) {
            int q = t + j * 256;
            int r = q >> 2;
            int cq = (q & 3) * 4;
            int grow = row0 + r;
            unsigned int sa = (unsigned int)__cvta_generic_to_shared(&xs[buf][r][cq]);
            CP_ASYNC16(sa, x + (size_t)grow * F_IN + k0 + cq, grow < NN);
        }
        if (t < 64) {
            int r = t >> 2;
            int cq = (t & 3) * 4;
            unsigned int sa = (unsigned int)__cvta_generic_to_shared(&ws[buf][r][cq]);
            CP_ASYNC16(sa, W1 + (size_t)(k0 + r) * HH + cq, 1);
        }
    };

    float acc[4][4] = {};

    issue_tile(0, 0);
    CP_COMMIT();

    #pragma unroll 4
    for (int it = 0; it < NTILES; it++) {
        int buf = it & 1;
        if (it + 1 < NTILES) {
            issue_tile(it + 1, buf ^ 1);
            CP_COMMIT();
            CP_WAIT(1);
        } else {
            CP_WAIT(0);
        }
        __syncthreads();

        #pragma unroll
        for (int kk = 0; kk < KT; kk++) {
            float4 w = *reinterpret_cast<const float4*>(&ws[buf][kk][c0]);
            #pragma unroll
            for (int i = 0; i < 4; i++) {
                float xv = xs[buf][rg + 64 * i][kk];
                acc[i][0] = fmaf(xv, w.x, acc[i][0]);
                acc[i][1] = fmaf(xv, w.y, acc[i][1]);
                acc[i][2] = fmaf(xv, w.z, acc[i][2]);
                acc[i][3] = fmaf(xv, w.w, acc[i][3]);
            }
        }
        __syncthreads();
    }

    #pragma unroll
    for (int i = 0; i < 4; i++) {
        int row = row0 + rg + 64 * i;
        if (row < NN) {
            float4 h = make_float4(acc[i][0], acc[i][1], acc[i][2], acc[i][3]);
            *reinterpret_cast<float4*>(g_h1 + (size_t)row * HH + c0) = h;
        }
    }
}

// ---------------------------------------------------------------------------
// Layer-1 aggregation: 4 threads per node (one float4 slice each), CSR gather.
// out1[d] = dinv_d * ( dinv_d * h1[d] + sum_s dinv_s * h1[s] )
__global__ void __launch_bounds__(256) k_gather1() {
    int tid = blockIdx.x * blockDim.x + threadIdx.x;
    int i = tid >> 2;
    if (i >= NN) return;
    int p = tid & 3;

    int beg = g_rowptr[i];
    int end = g_rowptr[i + 1];
    float di = g_dinv[i];

    float4 self = *reinterpret_cast<const float4*>(g_h1 + (size_t)i * HH + p * 4);
    float4 acc = make_float4(di * self.x, di * self.y, di * self.z, di * self.w);

    int j = beg;
    for (; j + 1 < end; j += 2) {
        int s0 = g_csrc[j];
        int s1 = g_csrc[j + 1];
        float w0 = g_dinv[s0];
        float w1 = g_dinv[s1];
        float4 v0 = *reinterpret_cast<const float4*>(g_h1 + (size_t)s0 * HH + p * 4);
        float4 v1 = *reinterpret_cast<const float4*>(g_h1 + (size_t)s1 * HH + p * 4);
        acc.x = fmaf(w0, v0.x, acc.x); acc.y = fmaf(w0, v0.y, acc.y);
        acc.z = fmaf(w0, v0.z, acc.z); acc.w = fmaf(w0, v0.w, acc.w);
        acc.x = fmaf(w1, v1.x, acc.x); acc.y = fmaf(w1, v1.y, acc.y);
        acc.z = fmaf(w1, v1.z, acc.z); acc.w = fmaf(w1, v1.w, acc.w);
    }
    if (j < end) {
        int s0 = g_csrc[j];
        float w0 = g_dinv[s0];
        float4 v0 = *reinterpret_cast<const float4*>(g_h1 + (size_t)s0 * HH + p * 4);
        acc.x = fmaf(w0, v0.x, acc.x); acc.y = fmaf(w0, v0.y, acc.y);
        acc.z = fmaf(w0, v0.z, acc.z); acc.w = fmaf(w0, v0.w, acc.w);
    }

    float4 o = make_float4(di * acc.x, di * acc.y, di * acc.z, di * acc.w);
    *reinterpret_cast<float4*>(g_out1 + (size_t)i * HH + p * 4) = o;
}

// ---------------------------------------------------------------------------
// t2 = relu(out1 + b1) @ W2  (unnormalized; gather2 applies norm)
__global__ void k_transform2(const float* __restrict__ b1, const float* __restrict__ W2) {
    __shared__ float w2s[HH][CPAD];
    __shared__ float b1s[HH];
    if (threadIdx.x < HH * CC) {
        int k = threadIdx.x / CC, c = threadIdx.x % CC;
        w2s[k][c] = W2[threadIdx.x];
    }
    if (threadIdx.x < HH) b1s[threadIdx.x] = b1[threadIdx.x];
    if (threadIdx.x < HH) w2s[threadIdx.x][CC] = 0.0f;
    __syncthreads();

    int i = blockIdx.x * blockDim.x + threadIdx.x;
    if (i >= NN) return;

    float h[HH];
    #pragma unroll
    for (int k = 0; k < HH; k++) {
        float v = g_out1[(size_t)i * HH + k] + b1s[k];
        h[k] = v > 0.0f ? v : 0.0f;
    }
    #pragma unroll
    for (int c = 0; c < CPAD; c++) {
        float acc = 0.0f;
        #pragma unroll
        for (int k = 0; k < HH; k++)
            acc = fmaf(h[k], w2s[k][c], acc);
        g_t2[(size_t)i * CPAD + c] = acc;
    }
}

// ---------------------------------------------------------------------------
// Layer-2 aggregation + bias + log_softmax, fused. 2 threads per node.
__global__ void __launch_bounds__(256) k_gather2_fin(const float* __restrict__ b2,
                                                     float* __restrict__ out) {
    int tid = blockIdx.x * blockDim.x + threadIdx.x;
    int iraw = tid >> 1;
    bool valid = iraw < NN;
    int i = valid ? iraw : NN - 1;   // clamp: keep full warp for shfl
    int p = tid & 1;

    int beg = g_rowptr[i];
    int end = g_rowptr[i + 1];
    float di = g_dinv[i];

    float4 self = *reinterpret_cast<const float4*>(g_t2 + (size_t)i * CPAD + p * 4);
    float4 acc = make_float4(di * self.x, di * self.y, di * self.z, di * self.w);

    int j = beg;
    for (; j + 1 < end; j += 2) {
        int s0 = g_csrc[j];
        int s1 = g_csrc[j + 1];
        float w0 = g_dinv[s0];
        float w1 = g_dinv[s1];
        float4 v0 = *reinterpret_cast<const float4*>(g_t2 + (size_t)s0 * CPAD + p * 4);
        float4 v1 = *reinterpret_cast<const float4*>(g_t2 + (size_t)s1 * CPAD + p * 4);
        acc.x = fmaf(w0, v0.x, acc.x); acc.y = fmaf(w0, v0.y, acc.y);
        acc.z = fmaf(w0, v0.z, acc.z); acc.w = fmaf(w0, v0.w, acc.w);
        acc.x = fmaf(w1, v1.x, acc.x); acc.y = fmaf(w1, v1.y, acc.y);
        acc.z = fmaf(w1, v1.z, acc.z); acc.w = fmaf(w1, v1.w, acc.w);
    }
    if (j < end) {
        int s0 = g_csrc[j];
        float w0 = g_dinv[s0];
        float4 v0 = *reinterpret_cast<const float4*>(g_t2 + (size_t)s0 * CPAD + p * 4);
        acc.x = fmaf(w0, v0.x, acc.x); acc.y = fmaf(w0, v0.y, acc.y);
        acc.z = fmaf(w0, v0.z, acc.z); acc.w = fmaf(w0, v0.w, acc.w);
    }

    // logits for this thread's 4 class slots (slot 7 = padding -> -inf)
    float val[4];
    val[0] = di * acc.x; val[1] = di * acc.y; val[2] = di * acc.z; val[3] = di * acc.w;
    #pragma unroll
    for (int k = 0; k < 4; k++) {
        int c = p * 4 + k;
        val[k] = (c < CC) ? val[k] + b2[c] : -1e30f;
    }

    float m4 = fmaxf(fmaxf(val[0], val[1]), fmaxf(val[2], val[3]));
    float mo = __shfl_xor_sync(0xFFFFFFFFu, m4, 1);
    float m = fmaxf(m4, mo);

    float s4 = __expf(val[0] - m) + __expf(val[1] - m) +
               __expf(val[2] - m) + __expf(val[3] - m);
    float so = __shfl_xor_sync(0xFFFFFFFFu, s4, 1);
    float lse = m + __logf(s4 + so);

    if (valid) {
        #pragma unroll
        for (int k = 0; k < 4; k++) {
            int c = p * 4 + k;
            if (c < CC) out[(size_t)i * CC + c] = val[k] - lse;
        }
    }
}

// ---------------------------------------------------------------------------
extern "C" void kernel_launch(void* const* d_in, const int* in_sizes, int n_in,
                              void* d_out, int out_size) {
    const float* x    = (const float*)d_in[0];
    const int* eidx   = (const int*)d_in[1];
    const float* W1   = (const float*)d_in[2];
    const float* b1   = (const float*)d_in[3];
    const float* W2   = (const float*)d_in[4];
    const float* b2   = (const float*)d_in[5];
    float* out        = (float*)d_out;

    const int* src = eidx;        // edge_index[0]
    const int* dst = eidx + EE;   // edge_index[1]

    const int TB = 256;
    k_prep0<<<(NN + TB - 1) / TB, TB>>>();
    k_hist<<<(EE + TB - 1) / TB, TB>>>(dst);
    k_scan1<<<NSB, SB>>>();
    k_scan2<<<1, 256>>>();
    k_scan3<<<(NN + TB - 1) / TB, TB>>>();
    k_permute<<<(EE + TB - 1) / TB, TB>>>(src, dst);
    k_gemm1<<<(NN + GR - 1) / GR, 256>>>(x, W1);
    k_gather1<<<(NN * 4 + TB - 1) / TB, TB>>>();
    k_transform2<<<(NN + TB - 1) / TB, TB>>>(b1, W2);
    k_gather2_fin<<<(NN * 2 + TB - 1) / TB, TB>>>(b2, out);
}

// round 9
// speedup vs baseline: 2.0436x; 1.0070x over previous
#include <cuda_runtime.h>
#include <cuda_bf16.h>
#include <cstdint>

// Problem constants (fixed by reference)
#define NN 100000
#define EE 3200000
#define F_IN 512
#define HH 16
#define CC 7
#define CPAD 8

// GEMM1 tiling
#define GR 256
#define KT 16
#define NTILES (F_IN / KT)
#define XSS 20

// Scan config
#define SB 512
#define NSB ((NN + SB - 1) / SB)   // 196

// Scratch (device globals: allocation-free rule)
// g_cnt is zero at module load and re-zeroed at the END of each kernel_launch
// sequence (in k_gather2_fin), so every invocation starts from zeros.
__device__ int   g_cnt[NN];        // in-degree (excl self loop)
__device__ int   g_cursor[NN];     // permute cursors (seeded = rowptr each call)
__device__ int   g_rowptr[NN + 1]; // CSR row pointers (by dst)
__device__ int   g_bsum[NSB];
__device__ float g_dinv[NN];
__device__ int   g_csrc[EE];       // CSR src indices
__device__ float g_h1[NN * HH];    // x @ W1
__device__ float g_t2[NN * CPAD];  // relu(out1+b1) @ W2

#define CP_ASYNC16(smem_u32, gptr, valid)                                   \
    asm volatile("cp.async.cg.shared.global [%0], [%1], 16, %2;\n"          \
                 :: "r"(smem_u32), "l"(gptr), "r"((valid) ? 16 : 0))
#define CP_COMMIT() asm volatile("cp.async.commit_group;\n")
#define CP_WAIT(n)  asm volatile("cp.async.wait_group %0;\n" :: "n"(n))

// ---------------------------------------------------------------------------
__global__ void k_hist(const int* __restrict__ dst) {
    int e = blockIdx.x * blockDim.x + threadIdx.x;
    if (e < EE) atomicAdd(&g_cnt[dst[e]], 1);
}

// Block-local exclusive scan (Hillis-Steele) + block sums
__global__ void __launch_bounds__(SB) k_scan1() {
    __shared__ int sh[SB];
    int t = threadIdx.x;
    int i = blockIdx.x * SB + t;
    int v = (i < NN) ? g_cnt[i] : 0;
    sh[t] = v;
    __syncthreads();
    #pragma unroll
    for (int off = 1; off < SB; off <<= 1) {
        int add = (t >= off) ? sh[t - off] : 0;
        __syncthreads();
        sh[t] += add;
        __syncthreads();
    }
    if (i < NN) g_rowptr[i] = sh[t] - v;   // exclusive (local)
    if (t == SB - 1) g_bsum[blockIdx.x] = sh[SB - 1];
}

// Each block scans the 196 block sums in smem (cheap, redundant), then adds
// the offset, computes dinv, and seeds the permute cursor.
__global__ void __launch_bounds__(256) k_scan3() {
    __shared__ int sh[256];
    int t = threadIdx.x;
    int v = (t < NSB) ? g_bsum[t] : 0;
    sh[t] = v;
    __syncthreads();
    #pragma unroll
    for (int off = 1; off < 256; off <<= 1) {
        int add = (t >= off) ? sh[t - off] : 0;
        __syncthreads();
        sh[t] += add;
        __syncthreads();
    }
    int i = blockIdx.x * 256 + t;
    if (i < NN) {
        int blk = i / SB;
        int off = (blk == 0) ? 0 : sh[blk - 1];
        int rp = g_rowptr[i] + off;
        g_rowptr[i] = rp;
        g_cursor[i] = rp;
        g_dinv[i] = rsqrtf((float)g_cnt[i] + 1.0f);
    }
    if (i == 0) g_rowptr[NN] = EE;
}

// Permute edges into CSR-by-dst (cursor holds absolute position)
__global__ void k_permute(const int* __restrict__ src, const int* __restrict__ dst) {
    int e = blockIdx.x * blockDim.x + threadIdx.x;
    if (e >= EE) return;
    int pos = atomicAdd(&g_cursor[dst[e]], 1);
    g_csrc[pos] = src[e];
}

// ---------------------------------------------------------------------------
// h1 = x @ W1. 2-stage cp.async pipeline, 4x4 thread tile.
__global__ void __launch_bounds__(256, 4) k_gemm1(const float* __restrict__ x,
                                                  const float* __restrict__ W1) {
    __shared__ float xs[2][GR][XSS];
    __shared__ float ws[2][KT][HH];

    const int t = threadIdx.x;
    const int row0 = blockIdx.x * GR;
    const int rg = t >> 2;
    const int c0 = (t & 3) * 4;

    auto issue_tile = [&](int tile, int buf) {
        int k0 = tile * KT;
        #pragma unroll
        for (int j = 0; j < 4; j++) {
            int q = t + j * 256;
            int r = q >> 2;
            int cq = (q & 3) * 4;
            int grow = row0 + r;
            unsigned int sa = (unsigned int)__cvta_generic_to_shared(&xs[buf][r][cq]);
            CP_ASYNC16(sa, x + (size_t)grow * F_IN + k0 + cq, grow < NN);
        }
        if (t < 64) {
            int r = t >> 2;
            int cq = (t & 3) * 4;
            unsigned int sa = (unsigned int)__cvta_generic_to_shared(&ws[buf][r][cq]);
            CP_ASYNC16(sa, W1 + (size_t)(k0 + r) * HH + cq, 1);
        }
    };

    float acc[4][4] = {};

    issue_tile(0, 0);
    CP_COMMIT();

    #pragma unroll 4
    for (int it = 0; it < NTILES; it++) {
        int buf = it & 1;
        if (it + 1 < NTILES) {
            issue_tile(it + 1, buf ^ 1);
            CP_COMMIT();
            CP_WAIT(1);
        } else {
            CP_WAIT(0);
        }
        __syncthreads();

        #pragma unroll
        for (int kk = 0; kk < KT; kk++) {
            float4 w = *reinterpret_cast<const float4*>(&ws[buf][kk][c0]);
            #pragma unroll
            for (int i = 0; i < 4; i++) {
                float xv = xs[buf][rg + 64 * i][kk];
                acc[i][0] = fmaf(xv, w.x, acc[i][0]);
                acc[i][1] = fmaf(xv, w.y, acc[i][1]);
                acc[i][2] = fmaf(xv, w.z, acc[i][2]);
                acc[i][3] = fmaf(xv, w.w, acc[i][3]);
            }
        }
        __syncthreads();
    }

    #pragma unroll
    for (int i = 0; i < 4; i++) {
        int row = row0 + rg + 64 * i;
        if (row < NN) {
            float4 h = make_float4(acc[i][0], acc[i][1], acc[i][2], acc[i][3]);
            *reinterpret_cast<float4*>(g_h1 + (size_t)row * HH + c0) = h;
        }
    }
}

// ---------------------------------------------------------------------------
// Fused: layer-1 CSR gather + relu + bias + (h2 @ W2) -> t2.
// 4 threads per node; after the gather each thread obtains all 16 h values
// via a 12-shuffle butterfly (static indexing only) and computes 2 t2 cols.
__global__ void __launch_bounds__(256) k_gather1_t2(const float* __restrict__ b1,
                                                    const float* __restrict__ W2) {
    __shared__ float w2s[HH][CPAD];
    __shared__ float b1s[HH];
    if (threadIdx.x < HH * CC) {
        int k = threadIdx.x / CC, c = threadIdx.x % CC;
        w2s[k][c] = W2[threadIdx.x];
    }
    if (threadIdx.x < HH) {
        b1s[threadIdx.x] = b1[threadIdx.x];
        w2s[threadIdx.x][CC] = 0.0f;
    }
    __syncthreads();

    int tid = blockIdx.x * blockDim.x + threadIdx.x;
    int iraw = tid >> 2;
    bool valid = iraw < NN;
    int i = valid ? iraw : NN - 1;   // clamp: keep warp converged for shfl
    int p = tid & 3;

    int beg = g_rowptr[i];
    int end = g_rowptr[i + 1];
    float di = g_dinv[i];

    float4 self = *reinterpret_cast<const float4*>(g_h1 + (size_t)i * HH + p * 4);
    float4 acc = make_float4(di * self.x, di * self.y, di * self.z, di * self.w);

    int j = beg;
    for (; j + 1 < end; j += 2) {
        int s0 = g_csrc[j];
        int s1 = g_csrc[j + 1];
        float w0 = g_dinv[s0];
        float w1 = g_dinv[s1];
        float4 v0 = *reinterpret_cast<const float4*>(g_h1 + (size_t)s0 * HH + p * 4);
        float4 v1 = *reinterpret_cast<const float4*>(g_h1 + (size_t)s1 * HH + p * 4);
        acc.x = fmaf(w0, v0.x, acc.x); acc.y = fmaf(w0, v0.y, acc.y);
        acc.z = fmaf(w0, v0.z, acc.z); acc.w = fmaf(w0, v0.w, acc.w);
        acc.x = fmaf(w1, v1.x, acc.x); acc.y = fmaf(w1, v1.y, acc.y);
        acc.z = fmaf(w1, v1.z, acc.z); acc.w = fmaf(w1, v1.w, acc.w);
    }
    if (j < end) {
        int s0 = g_csrc[j];
        float w0 = g_dinv[s0];
        float4 v0 = *reinterpret_cast<const float4*>(g_h1 + (size_t)s0 * HH + p * 4);
        acc.x = fmaf(w0, v0.x, acc.x); acc.y = fmaf(w0, v0.y, acc.y);
        acc.z = fmaf(w0, v0.z, acc.z); acc.w = fmaf(w0, v0.w, acc.w);
    }

    // out1 slice + bias + relu (slice p covers k = 4p..4p+3)
    float4 hh;
    hh.x = fmaxf(di * acc.x + b1s[p * 4 + 0], 0.0f);
    hh.y = fmaxf(di * acc.y + b1s[p * 4 + 1], 0.0f);
    hh.z = fmaxf(di * acc.z + b1s[p * 4 + 2], 0.0f);
    hh.w = fmaxf(di * acc.w + b1s[p * 4 + 3], 0.0f);

    // butterfly: gather all 4 slices of this node into canonical order
    const unsigned FULL = 0xFFFFFFFFu;
    float4 o1;
    o1.x = __shfl_xor_sync(FULL, hh.x, 1);
    o1.y = __shfl_xor_sync(FULL, hh.y, 1);
    o1.z = __shfl_xor_sync(FULL, hh.z, 1);
    o1.w = __shfl_xor_sync(FULL, hh.w, 1);
    bool low1 = (p & 1) == 0;
    float4 a = low1 ? hh : o1;   // slice (p & ~1)
    float4 b = low1 ? o1 : hh;   // slice (p | 1)

    float4 pa, pb;
    pa.x = __shfl_xor_sync(FULL, a.x, 2);
    pa.y = __shfl_xor_sync(FULL, a.y, 2);
    pa.z = __shfl_xor_sync(FULL, a.z, 2);
    pa.w = __shfl_xor_sync(FULL, a.w, 2);
    pb.x = __shfl_xor_sync(FULL, b.x, 2);
    pb.y = __shfl_xor_sync(FULL, b.y, 2);
    pb.z = __shfl_xor_sync(FULL, b.z, 2);
    pb.w = __shfl_xor_sync(FULL, b.w, 2);
    bool low2 = (p & 2) == 0;
    float4 s0 = low2 ? a : pa;   // slice 0 (k 0..3)
    float4 s1 = low2 ? b : pb;   // slice 1 (k 4..7)
    float4 s2 = low2 ? pa : a;   // slice 2 (k 8..11)
    float4 s3 = low2 ? pb : b;   // slice 3 (k 12..15)

    float h[HH] = { s0.x, s0.y, s0.z, s0.w, s1.x, s1.y, s1.z, s1.w,
                    s2.x, s2.y, s2.z, s2.w, s3.x, s3.y, s3.z, s3.w };

    // this thread computes t2 columns 2p and 2p+1
    int c0 = p * 2;
    float r0 = 0.0f, r1 = 0.0f;
    #pragma unroll
    for (int k = 0; k < HH; k++) {
        r0 = fmaf(h[k], w2s[k][c0], r0);
        r1 = fmaf(h[k], w2s[k][c0 + 1], r1);
    }
    if (valid) {
        float2 r = make_float2(r0, r1);
        *reinterpret_cast<float2*>(g_t2 + (size_t)i * CPAD + c0) = r;
    }
}

// ---------------------------------------------------------------------------
// Layer-2 aggregation + bias + log_softmax, fused. 2 threads per node.
// Also re-zeroes g_cnt for the next invocation.
__global__ void __launch_bounds__(256) k_gather2_fin(const float* __restrict__ b2,
                                                     float* __restrict__ out) {
    int tid = blockIdx.x * blockDim.x + threadIdx.x;
    if (tid < NN) g_cnt[tid] = 0;    // reset for next call (grid covers 2*NN >= NN)

    int iraw = tid >> 1;
    bool valid = iraw < NN;
    int i = valid ? iraw : NN - 1;   // clamp: keep full warp for shfl
    int p = tid & 1;

    int beg = g_rowptr[i];
    int end = g_rowptr[i + 1];
    float di = g_dinv[i];

    float4 self = *reinterpret_cast<const float4*>(g_t2 + (size_t)i * CPAD + p * 4);
    float4 acc = make_float4(di * self.x, di * self.y, di * self.z, di * self.w);

    int j = beg;
    for (; j + 1 < end; j += 2) {
        int s0 = g_csrc[j];
        int s1 = g_csrc[j + 1];
        float w0 = g_dinv[s0];
        float w1 = g_dinv[s1];
        float4 v0 = *reinterpret_cast<const float4*>(g_t2 + (size_t)s0 * CPAD + p * 4);
        float4 v1 = *reinterpret_cast<const float4*>(g_t2 + (size_t)s1 * CPAD + p * 4);
        acc.x = fmaf(w0, v0.x, acc.x); acc.y = fmaf(w0, v0.y, acc.y);
        acc.z = fmaf(w0, v0.z, acc.z); acc.w = fmaf(w0, v0.w, acc.w);
        acc.x = fmaf(w1, v1.x, acc.x); acc.y = fmaf(w1, v1.y, acc.y);
        acc.z = fmaf(w1, v1.z, acc.z); acc.w = fmaf(w1, v1.w, acc.w);
    }
    if (j < end) {
        int s0 = g_csrc[j];
        float w0 = g_dinv[s0];
        float4 v0 = *reinterpret_cast<const float4*>(g_t2 + (size_t)s0 * CPAD + p * 4);
        acc.x = fmaf(w0, v0.x, acc.x); acc.y = fmaf(w0, v0.y, acc.y);
        acc.z = fmaf(w0, v0.z, acc.z); acc.w = fmaf(w0, v0.w, acc.w);
    }

    // logits for this thread's 4 class slots (slot 7 = padding -> -inf)
    float val[4];
    val[0] = di * acc.x; val[1] = di * acc.y; val[2] = di * acc.z; val[3] = di * acc.w;
    #pragma unroll
    for (int k = 0; k < 4; k++) {
        int c = p * 4 + k;
        val[k] = (c < CC) ? val[k] + b2[c] : -1e30f;
    }

    float m4 = fmaxf(fmaxf(val[0], val[1]), fmaxf(val[2], val[3]));
    float mo = __shfl_xor_sync(0xFFFFFFFFu, m4, 1);
    float m = fmaxf(m4, mo);

    float s4 = __expf(val[0] - m) + __expf(val[1] - m) +
               __expf(val[2] - m) + __expf(val[3] - m);
    float so = __shfl_xor_sync(0xFFFFFFFFu, s4, 1);
    float lse = m + __logf(s4 + so);

    if (valid) {
        #pragma unroll
        for (int k = 0; k < 4; k++) {
            int c = p * 4 + k;
            if (c < CC) out[(size_t)i * CC + c] = val[k] - lse;
        }
    }
}

// ---------------------------------------------------------------------------
extern "C" void kernel_launch(void* const* d_in, const int* in_sizes, int n_in,
                              void* d_out, int out_size) {
    const float* x    = (const float*)d_in[0];
    const int* eidx   = (const int*)d_in[1];
    const float* W1   = (const float*)d_in[2];
    const float* b1   = (const float*)d_in[3];
    const float* W2   = (const float*)d_in[4];
    const float* b2   = (const float*)d_in[5];
    float* out        = (float*)d_out;

    const int* src = eidx;        // edge_index[0]
    const int* dst = eidx + EE;   // edge_index[1]

    const int TB = 256;
    k_hist<<<(EE + TB - 1) / TB, TB>>>(dst);
    k_scan1<<<NSB, SB>>>();
    k_scan3<<<(NN + 255) / 256, 256>>>();
    k_permute<<<(EE + TB - 1) / TB, TB>>>(src, dst);
    k_gemm1<<<(NN + GR - 1) / GR, 256>>>(x, W1);
    k_gather1_t2<<<(NN * 4 + TB - 1) / TB, TB>>>(b1, W2);
    k_gather2_fin<<<(NN * 2 + TB - 1) / TB, TB>>>(b2, out);
}

// round 10
// speedup vs baseline: 2.1086x; 1.0318x over previous
#include <cuda_runtime.h>
#include <cuda_bf16.h>
#include <cstdint>

// Problem constants (fixed by reference)
#define NN 100000
#define EE 3200000
#define F_IN 512
#define HH 16
#define CC 7
#define CPAD 8

// GEMM1 tiling
#define GR 256
#define KT 16
#define NTILES (F_IN / KT)
#define XSS 20

// Scan config
#define SB 512
#define NSB ((NN + SB - 1) / SB)   // 196

// Scratch (device globals: allocation-free rule)
// g_cnt is zero at module load and re-zeroed at the END of each kernel_launch
// sequence (in k_gather2_fin), so every invocation starts from zeros.
__device__ int   g_cnt[NN];        // in-degree (excl self loop)
__device__ int   g_cursor[NN];     // permute cursors (seeded = rowptr each call)
__device__ int   g_rowptr[NN + 1]; // CSR row pointers (by dst)
__device__ int   g_bsum[NSB];
__device__ float g_dinv[NN];
__device__ int   g_csrc[EE];       // CSR src indices
__device__ float g_h1[NN * HH];    // x @ W1
__device__ float g_t2[NN * CPAD];  // relu(out1+b1) @ W2

#define CP_ASYNC16(smem_u32, gptr, valid)                                   \
    asm volatile("cp.async.cg.shared.global [%0], [%1], 16, %2;\n"          \
                 :: "r"(smem_u32), "l"(gptr), "r"((valid) ? 16 : 0))
#define CP_COMMIT() asm volatile("cp.async.commit_group;\n")
#define CP_WAIT(n)  asm volatile("cp.async.wait_group %0;\n" :: "n"(n))

// ---------------------------------------------------------------------------
// Histogram: 4 edges per thread (int4) -> 4 independent RED.ADD in flight.
__global__ void k_hist(const int* __restrict__ dst) {
    int base = (blockIdx.x * blockDim.x + threadIdx.x) * 4;
    if (base >= EE) return;
    int4 d4 = *reinterpret_cast<const int4*>(dst + base);
    atomicAdd(&g_cnt[d4.x], 1);
    atomicAdd(&g_cnt[d4.y], 1);
    atomicAdd(&g_cnt[d4.z], 1);
    atomicAdd(&g_cnt[d4.w], 1);
}

// Block-local exclusive scan (Hillis-Steele) + block sums
__global__ void __launch_bounds__(SB) k_scan1() {
    __shared__ int sh[SB];
    int t = threadIdx.x;
    int i = blockIdx.x * SB + t;
    int v = (i < NN) ? g_cnt[i] : 0;
    sh[t] = v;
    __syncthreads();
    #pragma unroll
    for (int off = 1; off < SB; off <<= 1) {
        int add = (t >= off) ? sh[t - off] : 0;
        __syncthreads();
        sh[t] += add;
        __syncthreads();
    }
    if (i < NN) g_rowptr[i] = sh[t] - v;   // exclusive (local)
    if (t == SB - 1) g_bsum[blockIdx.x] = sh[SB - 1];
}

// Each block scans the 196 block sums in smem (cheap, redundant), then adds
// the offset, computes dinv, and seeds the permute cursor.
__global__ void __launch_bounds__(256) k_scan3() {
    __shared__ int sh[256];
    int t = threadIdx.x;
    int v = (t < NSB) ? g_bsum[t] : 0;
    sh[t] = v;
    __syncthreads();
    #pragma unroll
    for (int off = 1; off < 256; off <<= 1) {
        int add = (t >= off) ? sh[t - off] : 0;
        __syncthreads();
        sh[t] += add;
        __syncthreads();
    }
    int i = blockIdx.x * 256 + t;
    if (i < NN) {
        int blk = i / SB;
        int off = (blk == 0) ? 0 : sh[blk - 1];
        int rp = g_rowptr[i] + off;
        g_rowptr[i] = rp;
        g_cursor[i] = rp;
        g_dinv[i] = rsqrtf((float)g_cnt[i] + 1.0f);
    }
    if (i == 0) g_rowptr[NN] = EE;
}

// Permute edges into CSR-by-dst. 4 edges/thread: 4 independent atomic chains.
__global__ void k_permute(const int* __restrict__ src, const int* __restrict__ dst) {
    int base = (blockIdx.x * blockDim.x + threadIdx.x) * 4;
    if (base >= EE) return;
    int4 d4 = *reinterpret_cast<const int4*>(dst + base);
    int4 s4 = *reinterpret_cast<const int4*>(src + base);
    int p0 = atomicAdd(&g_cursor[d4.x], 1);
    int p1 = atomicAdd(&g_cursor[d4.y], 1);
    int p2 = atomicAdd(&g_cursor[d4.z], 1);
    int p3 = atomicAdd(&g_cursor[d4.w], 1);
    g_csrc[p0] = s4.x;
    g_csrc[p1] = s4.y;
    g_csrc[p2] = s4.z;
    g_csrc[p3] = s4.w;
}

// ---------------------------------------------------------------------------
// h1 = x @ W1. 2-stage cp.async pipeline, 4x4 thread tile.
__global__ void __launch_bounds__(256, 4) k_gemm1(const float* __restrict__ x,
                                                  const float* __restrict__ W1) {
    __shared__ float xs[2][GR][XSS];
    __shared__ float ws[2][KT][HH];

    const int t = threadIdx.x;
    const int row0 = blockIdx.x * GR;
    const int rg = t >> 2;
    const int c0 = (t & 3) * 4;

    auto issue_tile = [&](int tile, int buf) {
        int k0 = tile * KT;
        #pragma unroll
        for (int j = 0; j < 4; j++) {
            int q = t + j * 256;
            int r = q >> 2;
            int cq = (q & 3) * 4;
            int grow = row0 + r;
            unsigned int sa = (unsigned int)__cvta_generic_to_shared(&xs[buf][r][cq]);
            CP_ASYNC16(sa, x + (size_t)grow * F_IN + k0 + cq, grow < NN);
        }
        if (t < 64) {
            int r = t >> 2;
            int cq = (t & 3) * 4;
            unsigned int sa = (unsigned int)__cvta_generic_to_shared(&ws[buf][r][cq]);
            CP_ASYNC16(sa, W1 + (size_t)(k0 + r) * HH + cq, 1);
        }
    };

    float acc[4][4] = {};

    issue_tile(0, 0);
    CP_COMMIT();

    #pragma unroll 4
    for (int it = 0; it < NTILES; it++) {
        int buf = it & 1;
        if (it + 1 < NTILES) {
            issue_tile(it + 1, buf ^ 1);
            CP_COMMIT();
            CP_WAIT(1);
        } else {
            CP_WAIT(0);
        }
        __syncthreads();

        #pragma unroll
        for (int kk = 0; kk < KT; kk++) {
            float4 w = *reinterpret_cast<const float4*>(&ws[buf][kk][c0]);
            #pragma unroll
            for (int i = 0; i < 4; i++) {
                float xv = xs[buf][rg + 64 * i][kk];
                acc[i][0] = fmaf(xv, w.x, acc[i][0]);
                acc[i][1] = fmaf(xv, w.y, acc[i][1]);
                acc[i][2] = fmaf(xv, w.z, acc[i][2]);
                acc[i][3] = fmaf(xv, w.w, acc[i][3]);
            }
        }
        __syncthreads();
    }

    #pragma unroll
    for (int i = 0; i < 4; i++) {
        int row = row0 + rg + 64 * i;
        if (row < NN) {
            float4 h = make_float4(acc[i][0], acc[i][1], acc[i][2], acc[i][3]);
            *reinterpret_cast<float4*>(g_h1 + (size_t)row * HH + c0) = h;
        }
    }
}

// ---------------------------------------------------------------------------
// Fused: layer-1 CSR gather + relu + bias + (h2 @ W2) -> t2.
// 4 threads per node; after the gather each thread obtains all 16 h values
// via a 12-shuffle butterfly (static indexing only) and computes 2 t2 cols.
__global__ void __launch_bounds__(256) k_gather1_t2(const float* __restrict__ b1,
                                                    const float* __restrict__ W2) {
    __shared__ float w2s[HH][CPAD];
    __shared__ float b1s[HH];
    if (threadIdx.x < HH * CC) {
        int k = threadIdx.x / CC, c = threadIdx.x % CC;
        w2s[k][c] = W2[threadIdx.x];
    }
    if (threadIdx.x < HH) {
        b1s[threadIdx.x] = b1[threadIdx.x];
        w2s[threadIdx.x][CC] = 0.0f;
    }
    __syncthreads();

    int tid = blockIdx.x * blockDim.x + threadIdx.x;
    int iraw = tid >> 2;
    bool valid = iraw < NN;
    int i = valid ? iraw : NN - 1;   // clamp: keep warp converged for shfl
    int p = tid & 3;

    int beg = g_rowptr[i];
    int end = g_rowptr[i + 1];
    float di = g_dinv[i];

    float4 self = *reinterpret_cast<const float4*>(g_h1 + (size_t)i * HH + p * 4);
    float4 acc = make_float4(di * self.x, di * self.y, di * self.z, di * self.w);

    int j = beg;
    for (; j + 1 < end; j += 2) {
        int s0 = g_csrc[j];
        int s1 = g_csrc[j + 1];
        float w0 = g_dinv[s0];
        float w1 = g_dinv[s1];
        float4 v0 = *reinterpret_cast<const float4*>(g_h1 + (size_t)s0 * HH + p * 4);
        float4 v1 = *reinterpret_cast<const float4*>(g_h1 + (size_t)s1 * HH + p * 4);
        acc.x = fmaf(w0, v0.x, acc.x); acc.y = fmaf(w0, v0.y, acc.y);
        acc.z = fmaf(w0, v0.z, acc.z); acc.w = fmaf(w0, v0.w, acc.w);
        acc.x = fmaf(w1, v1.x, acc.x); acc.y = fmaf(w1, v1.y, acc.y);
        acc.z = fmaf(w1, v1.z, acc.z); acc.w = fmaf(w1, v1.w, acc.w);
    }
    if (j < end) {
        int s0 = g_csrc[j];
        float w0 = g_dinv[s0];
        float4 v0 = *reinterpret_cast<const float4*>(g_h1 + (size_t)s0 * HH + p * 4);
        acc.x = fmaf(w0, v0.x, acc.x); acc.y = fmaf(w0, v0.y, acc.y);
        acc.z = fmaf(w0, v0.z, acc.z); acc.w = fmaf(w0, v0.w, acc.w);
    }

    // out1 slice + bias + relu (slice p covers k = 4p..4p+3)
    float4 hh;
    hh.x = fmaxf(di * acc.x + b1s[p * 4 + 0], 0.0f);
    hh.y = fmaxf(di * acc.y + b1s[p * 4 + 1], 0.0f);
    hh.z = fmaxf(di * acc.z + b1s[p * 4 + 2], 0.0f);
    hh.w = fmaxf(di * acc.w + b1s[p * 4 + 3], 0.0f);

    // butterfly: gather all 4 slices of this node into canonical order
    const unsigned FULL = 0xFFFFFFFFu;
    float4 o1;
    o1.x = __shfl_xor_sync(FULL, hh.x, 1);
    o1.y = __shfl_xor_sync(FULL, hh.y, 1);
    o1.z = __shfl_xor_sync(FULL, hh.z, 1);
    o1.w = __shfl_xor_sync(FULL, hh.w, 1);
    bool low1 = (p & 1) == 0;
    float4 a = low1 ? hh : o1;   // slice (p & ~1)
    float4 b = low1 ? o1 : hh;   // slice (p | 1)

    float4 pa, pb;
    pa.x = __shfl_xor_sync(FULL, a.x, 2);
    pa.y = __shfl_xor_sync(FULL, a.y, 2);
    pa.z = __shfl_xor_sync(FULL, a.z, 2);
    pa.w = __shfl_xor_sync(FULL, a.w, 2);
    pb.x = __shfl_xor_sync(FULL, b.x, 2);
    pb.y = __shfl_xor_sync(FULL, b.y, 2);
    pb.z = __shfl_xor_sync(FULL, b.z, 2);
    pb.w = __shfl_xor_sync(FULL, b.w, 2);
    bool low2 = (p & 2) == 0;
    float4 s0 = low2 ? a : pa;   // slice 0 (k 0..3)
    float4 s1 = low2 ? b : pb;   // slice 1 (k 4..7)
    float4 s2 = low2 ? pa : a;   // slice 2 (k 8..11)
    float4 s3 = low2 ? pb : b;   // slice 3 (k 12..15)

    float h[HH] = { s0.x, s0.y, s0.z, s0.w, s1.x, s1.y, s1.z, s1.w,
                    s2.x, s2.y, s2.z, s2.w, s3.x, s3.y, s3.z, s3.w };

    // this thread computes t2 columns 2p and 2p+1
    int c0 = p * 2;
    float r0 = 0.0f, r1 = 0.0f;
    #pragma unroll
    for (int k = 0; k < HH; k++) {
        r0 = fmaf(h[k], w2s[k][c0], r0);
        r1 = fmaf(h[k], w2s[k][c0 + 1], r1);
    }
    if (valid) {
        float2 r = make_float2(r0, r1);
        *reinterpret_cast<float2*>(g_t2 + (size_t)i * CPAD + c0) = r;
    }
}

// ---------------------------------------------------------------------------
// Layer-2 aggregation + bias + log_softmax, fused. 2 threads per node.
// Also re-zeroes g_cnt for the next invocation.
__global__ void __launch_bounds__(256) k_gather2_fin(const float* __restrict__ b2,
                                                     float* __restrict__ out) {
    int tid = blockIdx.x * blockDim.x + threadIdx.x;
    if (tid < NN) g_cnt[tid] = 0;    // reset for next call (grid covers 2*NN >= NN)

    int iraw = tid >> 1;
    bool valid = iraw < NN;
    int i = valid ? iraw : NN - 1;   // clamp: keep full warp for shfl
    int p = tid & 1;

    int beg = g_rowptr[i];
    int end = g_rowptr[i + 1];
    float di = g_dinv[i];

    float4 self = *reinterpret_cast<const float4*>(g_t2 + (size_t)i * CPAD + p * 4);
    float4 acc = make_float4(di * self.x, di * self.y, di * self.z, di * self.w);

    int j = beg;
    for (; j + 1 < end; j += 2) {
        int s0 = g_csrc[j];
        int s1 = g_csrc[j + 1];
        float w0 = g_dinv[s0];
        float w1 = g_dinv[s1];
        float4 v0 = *reinterpret_cast<const float4*>(g_t2 + (size_t)s0 * CPAD + p * 4);
        float4 v1 = *reinterpret_cast<const float4*>(g_t2 + (size_t)s1 * CPAD + p * 4);
        acc.x = fmaf(w0, v0.x, acc.x); acc.y = fmaf(w0, v0.y, acc.y);
        acc.z = fmaf(w0, v0.z, acc.z); acc.w = fmaf(w0, v0.w, acc.w);
        acc.x = fmaf(w1, v1.x, acc.x); acc.y = fmaf(w1, v1.y, acc.y);
        acc.z = fmaf(w1, v1.z, acc.z); acc.w = fmaf(w1, v1.w, acc.w);
    }
    if (j < end) {
        int s0 = g_csrc[j];
        float w0 = g_dinv[s0];
        float4 v0 = *reinterpret_cast<const float4*>(g_t2 + (size_t)s0 * CPAD + p * 4);
        acc.x = fmaf(w0, v0.x, acc.x); acc.y = fmaf(w0, v0.y, acc.y);
        acc.z = fmaf(w0, v0.z, acc.z); acc.w = fmaf(w0, v0.w, acc.w);
    }

    // logits for this thread's 4 class slots (slot 7 = padding -> -inf)
    float val[4];
    val[0] = di * acc.x; val[1] = di * acc.y; val[2] = di * acc.z; val[3] = di * acc.w;
    #pragma unroll
    for (int k = 0; k < 4; k++) {
        int c = p * 4 + k;
        val[k] = (c < CC) ? val[k] + b2[c] : -1e30f;
    }

    float m4 = fmaxf(fmaxf(val[0], val[1]), fmaxf(val[2], val[3]));
    float mo = __shfl_xor_sync(0xFFFFFFFFu, m4, 1);
    float m = fmaxf(m4, mo);

    float s4 = __expf(val[0] - m) + __expf(val[1] - m) +
               __expf(val[2] - m) + __expf(val[3] - m);
    float so = __shfl_xor_sync(0xFFFFFFFFu, s4, 1);
    float lse = m + __logf(s4 + so);

    if (valid) {
        #pragma unroll
        for (int k = 0; k < 4; k++) {
            int c = p * 4 + k;
            if (c < CC) out[(size_t)i * CC + c] = val[k] - lse;
        }
    }
}

// ---------------------------------------------------------------------------
extern "C" void kernel_launch(void* const* d_in, const int* in_sizes, int n_in,
                              void* d_out, int out_size) {
    const float* x    = (const float*)d_in[0];
    const int* eidx   = (const int*)d_in[1];
    const float* W1   = (const float*)d_in[2];
    const float* b1   = (const float*)d_in[3];
    const float* W2   = (const float*)d_in[4];
    const float* b2   = (const float*)d_in[5];
    float* out        = (float*)d_out;

    const int* src = eidx;        // edge_index[0]
    const int* dst = eidx + EE;   // edge_index[1]

    const int TB = 256;
    k_hist<<<(EE / 4 + TB - 1) / TB, TB>>>(dst);
    k_scan1<<<NSB, SB>>>();
    k_scan3<<<(NN + 255) / 256, 256>>>();
    k_permute<<<(EE / 4 + TB - 1) / TB, TB>>>(src, dst);
    k_gemm1<<<(NN + GR - 1) / GR, 256>>>(x, W1);
    k_gather1_t2<<<(NN * 4 + TB - 1) / TB, TB>>>(b1, W2);
    k_gather2_fin<<<(NN * 2 + TB - 1) / TB, TB>>>(b2, out);
}